// round 10
// baseline (speedup 1.0000x reference)
#include <cuda_runtime.h>

// SAXS P(r) L1 loss — Round 6.
// vs R5: packed-bin private histograms (word w = bins 2w|2w+1, u16 fields)
// halve per-thread smem to 416B -> 256-thread blocks, 16 warps/SM (2x warps
// per SMSP) to bury the LDS RMW latency. Pair (lo,lo+1): even lo = 1 RMW,
// odd lo = 2 RMWs (branchless, 2nd RMW -> trash word when even). Sequential
// per-thread RMWs = program-order safe, merge network removed. Banks stay
// conflict-free (bank == tid&31). Finalize fused via atomic ticket.

namespace {
constexpr int   kNBins      = 201;
constexpr int   kNAtoms     = 9472;                       // 256*37
constexpr int   kTile       = 128;
constexpr int   kNTiles     = kNAtoms / kTile;            // 74
constexpr int   kNPairTiles = kNTiles * (kNTiles + 1) / 2;   // 2775
constexpr int   kBlocksX    = 148;                        // 1 wave @ 2 blocks/SM
constexpr float kPre        = 512.0f;                     // 256 / STEP
constexpr float kClampT     = 51966.0f;                   // masked -> word 101 (trash)
constexpr int   kWords      = 104;                        // 0..100 live, 101-103 trash
constexpr int   kThreads    = 256;
constexpr int   kHistBytes  = kWords * kThreads * 4;      // 106496
constexpr int   kSmemBytes  = kHistBytes + 2 * 256 * 16;  // +8192 = 114688 (112KB)
constexpr unsigned kTrashOff = 103u * 1024u;              // word 103 byte offset
constexpr unsigned kDiagOff  = 102u * 1024u;              // word 102 byte offset
}

__device__ float4       g_pos[2][kNAtoms];
__device__ unsigned int g_hist[2][256];
__device__ unsigned int g_done;

// ---------------------------------------------------------------------------
__global__ void prepack_kernel(const float* __restrict__ pred,
                               const float* __restrict__ tru,
                               const float* __restrict__ mask) {
    int i = blockIdx.x * blockDim.x + threadIdx.x;
    if (i == 0) g_done = 0u;
    if (i < 512) ((unsigned int*)g_hist)[i] = 0u;
    if (i >= kNAtoms) return;
    float m = mask[i];
    if (m != 0.0f) {
        g_pos[0][i] = make_float4(pred[3*i+0]*kPre, pred[3*i+1]*kPre, pred[3*i+2]*kPre, 0.f);
        g_pos[1][i] = make_float4(tru [3*i+0]*kPre, tru [3*i+1]*kPre, tru [3*i+2]*kPre, 0.f);
    } else {
        float dx = 1.0e8f + (float)i * 2.0e5f;   // displaced -> clamp -> trash word
        g_pos[0][i] = make_float4(dx, 0.f, 0.f, 0.f);
        g_pos[1][i] = make_float4(dx, 0.f, 0.f, 0.f);
    }
}

// ---------------------------------------------------------------------------
__device__ __forceinline__ void decode_tile(int p, int& bi, int& bj) {
    double Td = (double)kNTiles;
    int b = (int)(((2.0 * Td + 1.0) -
                   sqrt((2.0 * Td + 1.0) * (2.0 * Td + 1.0) - 8.0 * (double)p)) * 0.5);
    if (b < 0) b = 0;
    if (b > kNTiles - 1) b = kNTiles - 1;
    while (b * (2 * kNTiles - b + 1) / 2 > p) --b;
    while ((b + 1) * (2 * kNTiles - b) / 2 <= p) ++b;
    bi = b;
    bj = b + (p - b * (2 * kNTiles - b + 1) / 2);
}

// One pair: distance -> (off0,val0) + (off1,val1); off1 = trash when lo even.
__device__ __forceinline__ void pair_update(char* hb,
                                            float ax, float ay, float az,
                                            const float3 rj, bool kill) {
    float dx = ax - rj.x;
    float dy = ay - rj.y;
    float dz = az - rj.z;
    float d2 = fmaf(dx, dx, fmaf(dy, dy, dz * dz));
    float t  = fminf(d2 * rsqrtf(d2), kClampT);         // d*256/STEP; NaN -> clamp
    int   b  = __float_as_int(t + 12582912.0f);         // round-to-nearest in mantissa
    unsigned q   = (unsigned)b & 255u;
    bool     odd = (b & 256) != 0;
    unsigned off0 = ((unsigned)b & 0x1FE00u) << 1;      // (b>>9)*1024: word byte off
    // even: one packed RMW (low=256-q -> bin 2w, high=q -> bin 2w+1)
    // odd : high of w += 256-q (bin lo), low of w+1 += q (bin lo+1)
    unsigned val0 = odd ? (16777216u - (q << 16)) : (q * 65535u + 256u);
    unsigned off1 = odd ? (off0 + 1024u) : kTrashOff;
    if (kill) { off0 = kDiagOff; off1 = kTrashOff; }    // diagonal / self pairs
    unsigned a0 = *(unsigned*)(hb + off0);
    unsigned a1 = *(unsigned*)(hb + off1);
    *(unsigned*)(hb + off0) = a0 + val0;
    *(unsigned*)(hb + off1) = a1 + q;
}

// ---------------------------------------------------------------------------
__global__ __launch_bounds__(kThreads, 2)
void pair_hist_kernel(float* __restrict__ out) {
    extern __shared__ unsigned int smem[];
    unsigned int* hist = smem;                            // [104][256]
    float4* buf = (float4*)(smem + kWords * kThreads);    // [2][256] float4

    const int s   = blockIdx.y;
    const int tid = threadIdx.x;
    const int tx  = tid & 15;     // cols tx*8 + v
    const int ty  = tid >> 4;     // rows ty*8 + u
    char* hb = (char*)hist + tid * 4;                     // bank = tid&31

#pragma unroll 4
    for (int w = 0; w < kWords; ++w) hist[(w << 8) + tid] = 0u;

    int p = blockIdx.x;
    int bi, bj;
    decode_tile(p, bi, bj);
    {
        int idx = (tid < 128) ? (bi * kTile + tid) : (bj * kTile + tid - 128);
        buf[tid] = g_pos[s][idx];
    }
    int cur = 0;
    __syncthreads();

    for (;;) {
        const int pn = p + kBlocksX;
        const bool havenext = (pn < kNPairTiles);
        float4 nxt; int bin_ = 0, bjn = 0;
        if (havenext) {
            decode_tile(pn, bin_, bjn);
            int idx = (tid < 128) ? (bin_ * kTile + tid) : (bjn * kTile + tid - 128);
            nxt = g_pos[s][idx];
        }

        const float4* ti = buf + cur * 256;
        const float4* tj = ti + 128;
        float3 ri[8], rj[8];
#pragma unroll
        for (int u = 0; u < 8; ++u) {
            float4 t4 = ti[ty * 8 + u];
            ri[u] = make_float3(t4.x, t4.y, t4.z);
        }
#pragma unroll
        for (int v = 0; v < 8; ++v) {
            float4 t4 = tj[tx * 8 + v];
            rj[v] = make_float3(t4.x, t4.y, t4.z);
        }

        if (bi != bj) {
#pragma unroll
            for (int u = 0; u < 8; ++u)
#pragma unroll
                for (int v = 0; v < 8; ++v)
                    pair_update(hb, ri[u].x, ri[u].y, ri[u].z, rj[v], false);
        } else {
#pragma unroll
            for (int u = 0; u < 8; ++u) {
                const int iu = ty * 8 + u;
#pragma unroll
                for (int v = 0; v < 8; ++v)
                    pair_update(hb, ri[u].x, ri[u].y, ri[u].z, rj[v],
                                iu >= tx * 8 + v);        // strict upper triangle
            }
        }

        __syncthreads();
        if (!havenext) break;
        buf[(cur ^ 1) * 256 + tid] = nxt;
        __syncthreads();
        cur ^= 1; p = pn; bi = bin_; bj = bjn;
    }

    // ---- flush: word w -> bins (2w, 2w+1); bin201 (hi of w=100) folds to 200
    if (tid < 101) {
        const int w = tid;
        unsigned slo = 0, shi = 0;
        for (int i = 0; i < kThreads; ++i) {
            int t = (tid + i) & 255;                      // staggered, conflict-free
            unsigned v = hist[(w << 8) + t];
            slo += v & 0xFFFFu;
            shi += v >> 16;
        }
        int b0 = 2 * w;
        if (b0 == 200) { if (slo + shi) atomicAdd(&g_hist[s][200], slo + shi); }
        else {
            if (slo) atomicAdd(&g_hist[s][b0], slo);
            if (shi) atomicAdd(&g_hist[s][b0 + 1], shi);
        }
    }

    // ---- last block finalizes ----
    __threadfence();
    __shared__ unsigned int ticket;
    __syncthreads();
    if (tid == 0) ticket = atomicAdd(&g_done, 1u);
    __syncthreads();
    if (ticket != 2u * kBlocksX - 1u) return;
    __threadfence();

    double* sh = (double*)smem;                           // reuse dead hist smem
    volatile unsigned int* gh = (volatile unsigned int*)g_hist;
    double h0 = (tid < kNBins) ? (double)gh[tid]       : 0.0;
    double h1 = (tid < kNBins) ? (double)gh[256 + tid] : 0.0;

    sh[tid] = h0; __syncthreads();
    for (int o = 128; o > 0; o >>= 1) { if (tid < o) sh[tid] += sh[tid + o]; __syncthreads(); }
    double s0 = sh[0]; __syncthreads();

    sh[tid] = h1; __syncthreads();
    for (int o = 128; o > 0; o >>= 1) { if (tid < o) sh[tid] += sh[tid + o]; __syncthreads(); }
    double s1 = sh[0]; __syncthreads();

    sh[tid] = fabs(h0 / (s0 + 1e-12) - h1 / (s1 + 1e-12)); __syncthreads();
    for (int o = 128; o > 0; o >>= 1) { if (tid < o) sh[tid] += sh[tid + o]; __syncthreads(); }

    if (tid == 0) out[0] = (float)sh[0];
}

// ---------------------------------------------------------------------------
extern "C" void kernel_launch(void* const* d_in, const int* in_sizes, int n_in,
                              void* d_out, int out_size) {
    (void)in_sizes; (void)n_in; (void)out_size;
    const float* pred = (const float*)d_in[0];
    const float* tru  = (const float*)d_in[1];
    const float* mask = (const float*)d_in[2];

    cudaFuncSetAttribute(pair_hist_kernel,
                         cudaFuncAttributeMaxDynamicSharedMemorySize, kSmemBytes);

    prepack_kernel<<<(kNAtoms + 255) / 256, 256>>>(pred, tru, mask);

    dim3 grid(kBlocksX, 2);
    pair_hist_kernel<<<grid, kThreads, kSmemBytes>>>((float*)d_out);
}